// round 7
// baseline (speedup 1.0000x reference)
#include <cuda_runtime.h>
#include <cuda_bf16.h>
#include <cstdint>

// DIN fused kernels for sm_103a — round 7 (round 6 + producer loop-bound fix).
// K1: warp-specialized persistent attention: 6 consumer warps (bf16 mma.sync,
//     2 col-groups x 3 row-groups) + 2 producer warps (LDG->cvt->STS next batch,
//     cand gemv). Double-buffered bf16 X. 1 full barrier per batch.
// K2: MLP (fp32).

#define S_LEN 200
#define E_DIM 128
#define XSTRB 272        // bf16 X row stride bytes (odd 16B units -> LDSM conflict-free)

// ---- K1 smem byte offsets ----
#define XBF0_OFF   0          // 208 x 136 bf16 = 56576 (rows 200-207 zero)
#define XBF1_OFF   56576
#define WC_OFF     113152     // 128 x 132 bf16 W_c^T [n][e] = 33792
#define VBUF_OFF   146944     // float[2][128]
#define PART_OFF   147968     // float[960]
#define RED_OFF    151808     // float[64]
#define CANDS_OFF  152064     // float[2][128]
#define B1_OFF     153088     // float[128]
#define SMEM_REQ   153600

__device__ float g_ui[4096 * 128];   // user_interest

__device__ __forceinline__ uint32_t smem_u32(const void* p) {
    uint32_t a;
    asm("{ .reg .u64 t; cvta.to.shared.u64 t, %1; cvt.u32.u64 %0, t; }"
        : "=r"(a) : "l"(p));
    return a;
}
__device__ __forceinline__ uint32_t packbf(float lo, float hi) {
    uint32_t r;  // first f32 source -> high half
    asm("cvt.rn.bf16x2.f32 %0, %1, %2;" : "=r"(r) : "f"(hi), "f"(lo));
    return r;
}
__device__ __forceinline__ void mma16(float* d, const uint32_t* a, const uint32_t* b) {
    asm volatile(
        "mma.sync.aligned.m16n8k16.row.col.f32.bf16.bf16.f32 "
        "{%0,%1,%2,%3}, {%4,%5,%6,%7}, {%8,%9}, {%0,%1,%2,%3};"
        : "+f"(d[0]), "+f"(d[1]), "+f"(d[2]), "+f"(d[3])
        : "r"(a[0]), "r"(a[1]), "r"(a[2]), "r"(a[3]), "r"(b[0]), "r"(b[1]));
}
__device__ __forceinline__ void ldsm4(uint32_t* r, uint32_t addr) {
    asm volatile("ldmatrix.sync.aligned.m8n8.x4.shared.b16 {%0,%1,%2,%3}, [%4];"
                 : "=r"(r[0]), "=r"(r[1]), "=r"(r[2]), "=r"(r[3]) : "r"(addr));
}
#define CBAR() asm volatile("bar.sync 1, 192;" ::: "memory")
#define PBAR() asm volatile("bar.sync 2, 64;" ::: "memory")

// ---------------------------------------------------------------------------
// K1
// ---------------------------------------------------------------------------
__global__ __launch_bounds__(256, 1) void din_attn_kernel(
    const float* __restrict__ beh, const float* __restrict__ cand,
    const float* __restrict__ fc1w, const float* __restrict__ fc1b,
    const float* __restrict__ fc2w, int nb)
{
    extern __shared__ __align__(16) char Ab[];
    const uint32_t A = smem_u32(Ab);

    float* vbuf  = (float*)(Ab + VBUF_OFF);
    float* part  = (float*)(Ab + PART_OFF);
    float* red   = (float*)(Ab + RED_OFF);
    float* cands = (float*)(Ab + CANDS_OFF);
    float* b1s   = (float*)(Ab + B1_OFF);

    const int tid = threadIdx.x, wid = tid >> 5, lane = tid & 31;
    const int g = lane >> 2, t4 = lane & 3;
    const int stride = gridDim.x;
    const int b0 = blockIdx.x;
    if (b0 >= nb) return;

    const bool is_cons = (tid < 192);
    const int cg = wid & 1;                 // consumer col-group (64 cols)
    const int rg = wid >> 1;                // consumer row-group (0..2)
    const int n0c = cg * 64;
    const int mt_begin = (rg == 0) ? 0 : (rg == 1) ? 5 : 9;
    const int mt_end   = (rg == 0) ? 5 : (rg == 1) ? 9 : 13;

    // ================= one-time init =================
    {   // stage W_b fp32 into smem base (64KB over XBF region)
        const float4* w4 = (const float4*)fc1w;
        float4* s4 = (float4*)Ab;
#pragma unroll
        for (int i = 0; i < 16; i++) s4[tid + i * 256] = w4[tid + i * 256];
    }
    __syncthreads();

    uint32_t Bf[8][8][2];
    float w2v[8][2];
    if (is_cons) {
        const float* stgF = (const float*)Ab;
#pragma unroll
        for (int kt = 0; kt < 8; kt++)
#pragma unroll
            for (int nt = 0; nt < 8; nt++) {
                int n = n0c + nt * 8 + g;
                int r = kt * 16 + 2 * t4;
                Bf[kt][nt][0] = packbf(stgF[r * 128 + n],       stgF[(r + 1) * 128 + n]);
                Bf[kt][nt][1] = packbf(stgF[(r + 8) * 128 + n], stgF[(r + 9) * 128 + n]);
            }
#pragma unroll
        for (int nt = 0; nt < 8; nt++) {
            w2v[nt][0] = fc2w[n0c + nt * 8 + 2 * t4];
            w2v[nt][1] = fc2w[n0c + nt * 8 + 2 * t4 + 1];
        }
    }
    __syncthreads();   // W_b staging consumed

    // W_c -> bf16 [n][e] stride 132; b1; zero phantom rows of both X buffers
    for (int idx = tid; idx < 128 * 128; idx += 256) {
        int e = idx >> 7, n = idx & 127;
        *(__nv_bfloat16*)(Ab + WC_OFF + (uint32_t)(n * 132 + e) * 2) =
            __float2bfloat16_rn(fc1w[128 * 128 + idx]);
    }
    if (tid < 128) b1s[tid] = fc1b[tid];
    for (int i = tid; i < 1088; i += 256) {
        *(uint16_t*)(Ab + XBF0_OFF + 200 * XSTRB + i * 2) = 0;
        *(uint16_t*)(Ab + XBF1_OFF + 200 * XSTRB + i * 2) = 0;
    }
    // prologue: fill XBF[0] + cands[0] with batch b0 (all 256 threads)
    {
        const float4* src = (const float4*)(beh + (size_t)b0 * (S_LEN * E_DIM));
#pragma unroll
        for (int it = 0; it < 25; it++) {
            int i = tid + it * 256;
            float4 v = src[i];
            int s = i >> 5, e0 = (i & 31) * 4;
            *(uint2*)(Ab + XBF0_OFF + (uint32_t)s * XSTRB + (uint32_t)e0 * 2) =
                make_uint2(packbf(v.x, v.y), packbf(v.z, v.w));
        }
        if (tid < 32)
            ((float4*)cands)[tid] = ((const float4*)(cand + (size_t)b0 * 128))[tid];
    }
    __syncthreads();
    {   // prologue gemv: vbuf[0] = cand @ W_c + b1  (256 threads, half-row each)
        int n = tid >> 1, h2 = tid & 1;
        const uint32_t* wrow = (const uint32_t*)(Ab + WC_OFF) + n * 66 + h2 * 32;
        const float2* cd = (const float2*)cands + h2 * 32;
        float a = 0.f;
#pragma unroll 8
        for (int k = 0; k < 32; k++) {
            uint32_t wv = wrow[k];
            __nv_bfloat162 p = *reinterpret_cast<__nv_bfloat162*>(&wv);
            float2 c = cd[k];
            a += c.x * __bfloat162float(p.x) + c.y * __bfloat162float(p.y);
        }
        a += __shfl_xor_sync(0xffffffffu, a, 1);
        if (h2 == 0) vbuf[n] = a + b1s[n];
    }
    __syncthreads();

    const uint32_t lm_lane = (uint32_t)(lane & 15) * XSTRB + ((lane & 16) ? 16u : 0u);

    // ================= main loop =================
    int i = 0;
    for (int b = b0; b < nb; b += stride, i++) {
        const int par = i & 1;
        const uint32_t xoffb = par ? XBF1_OFF : XBF0_OFF;

        if (is_cons) {
            // ---------- consumer: batch b from XBF[par], vbuf[par] ----------
            const float* vb = vbuf + par * 128;
            float2 vv[8];
#pragma unroll
            for (int nt = 0; nt < 8; nt++)
                vv[nt] = *(const float2*)(vb + n0c + nt * 8 + 2 * t4);

            const uint32_t lm_base = A + xoffb + lm_lane;
            for (int mt = mt_begin; mt < mt_end; mt++) {
                uint32_t abase = lm_base + (uint32_t)mt * 16u * XSTRB;
                float acc[8][4];
#pragma unroll
                for (int nt = 0; nt < 8; nt++)
#pragma unroll
                    for (int j = 0; j < 4; j++) acc[nt][j] = 0.f;
#pragma unroll
                for (int kt = 0; kt < 8; kt++) {
                    uint32_t a[4];
                    ldsm4(a, abase + (uint32_t)kt * 32u);
#pragma unroll
                    for (int nt = 0; nt < 8; nt++)
                        mma16(acc[nt], a, Bf[kt][nt]);
                }
                float p0 = 0.f, p1 = 0.f;
#pragma unroll
                for (int nt = 0; nt < 8; nt++) {
                    p0 += fmaxf(acc[nt][0] + vv[nt].x, 0.f) * w2v[nt][0]
                        + fmaxf(acc[nt][1] + vv[nt].y, 0.f) * w2v[nt][1];
                    p1 += fmaxf(acc[nt][2] + vv[nt].x, 0.f) * w2v[nt][0]
                        + fmaxf(acc[nt][3] + vv[nt].y, 0.f) * w2v[nt][1];
                }
                p0 += __shfl_xor_sync(0xffffffffu, p0, 1);
                p0 += __shfl_xor_sync(0xffffffffu, p0, 2);
                p1 += __shfl_xor_sync(0xffffffffu, p1, 1);
                p1 += __shfl_xor_sync(0xffffffffu, p1, 2);
                if (t4 == 0) {
                    int r_lo = mt * 16 + g, r_hi = mt * 16 + 8 + g;
                    part[cg * 208 + r_lo] = p0;
                    if (r_hi < S_LEN) part[cg * 208 + r_hi] = p1;
                }
            }
            CBAR();

            // ---------- softmax over 200 scores (192 threads) ----------
            float sc1 = part[tid] + part[208 + tid];
            float sc2 = (tid < 8) ? (part[192 + tid] + part[400 + tid]) : -3.4e38f;
            float mx = fmaxf(sc1, sc2);
#pragma unroll
            for (int o = 16; o; o >>= 1)
                mx = fmaxf(mx, __shfl_xor_sync(0xffffffffu, mx, o));
            if (lane == 0) red[wid] = mx;
            CBAR();
            mx = red[0];
#pragma unroll
            for (int w = 1; w < 6; w++) mx = fmaxf(mx, red[w]);
            float ex1 = __expf(sc1 - mx);
            float ex2 = (tid < 8) ? __expf(sc2 - mx) : 0.f;
            float sum = ex1 + ex2;
#pragma unroll
            for (int o = 16; o; o >>= 1)
                sum += __shfl_xor_sync(0xffffffffu, sum, o);
            if (lane == 0) red[8 + wid] = sum;
            CBAR();
            sum = 0.f;
#pragma unroll
            for (int w = 0; w < 6; w++) sum += red[8 + w];
            float inv = 1.f / sum;
            part[tid] = ex1 * inv;
            if (tid < 8) part[192 + tid] = ex2 * inv;
            CBAR();

            // ---------- user_interest = attn @ X ----------
            if (tid < 128) {
                int e = tid;
                float acc = 0.f;
#pragma unroll 4
                for (int s = 0; s < 100; s++)
                    acc += part[s] * __bfloat162float(
                        *(const __nv_bfloat16*)(Ab + xoffb + (uint32_t)s * XSTRB + (uint32_t)e * 2));
                CBAR();
                g_ui[(size_t)b * 128 + e] = acc + part[832 + e];
            } else {
                int eA = tid - 128, eB = eA + 64;
                float aA = 0.f, aB = 0.f;
#pragma unroll 4
                for (int s = 100; s < 200; s++) {
                    float w = part[s];
                    aA += w * __bfloat162float(
                        *(const __nv_bfloat16*)(Ab + xoffb + (uint32_t)s * XSTRB + (uint32_t)eA * 2));
                    aB += w * __bfloat162float(
                        *(const __nv_bfloat16*)(Ab + xoffb + (uint32_t)s * XSTRB + (uint32_t)eB * 2));
                }
                part[832 + eA] = aA;
                part[832 + eB] = aB;
                CBAR();
            }
        } else {
            // ---------- producer: fill XBF[par^1] etc. for batch b+stride ----------
            const int bn = b + stride;
            if (bn < nb) {
                const int ptid = tid - 192;                 // 0..63
                const uint32_t xoffn = par ? XBF0_OFF : XBF1_OFF;
                float* candsN = cands + (par ^ 1) * 128;
                float* vbufN  = vbuf  + (par ^ 1) * 128;

                if (ptid < 32)
                    ((float4*)candsN)[ptid] =
                        ((const float4*)(cand + (size_t)bn * 128))[ptid];

                const float4* src = (const float4*)(beh + (size_t)bn * (S_LEN * E_DIM));
                // 6400 float4 total / 64 producer threads = 100 iterations
#pragma unroll 4
                for (int it = 0; it < 100; it++) {
                    int idx = ptid + it * 64;
                    float4 v = src[idx];
                    int s = idx >> 5, e0 = (idx & 31) * 4;
                    *(uint2*)(Ab + xoffn + (uint32_t)s * XSTRB + (uint32_t)e0 * 2) =
                        make_uint2(packbf(v.x, v.y), packbf(v.z, v.w));
                }
                PBAR();   // candsN visible to all 64 producer threads

                // v = cand @ W_c + b1 : each producer thread does 2 n-values
                int nA = ptid, nB = ptid + 64;
                const uint32_t* w0 = (const uint32_t*)(Ab + WC_OFF) + nA * 66;
                const uint32_t* w1 = (const uint32_t*)(Ab + WC_OFF) + nB * 66;
                const float2* cd = (const float2*)candsN;
                float a0 = 0.f, a1 = 0.f;
#pragma unroll 8
                for (int k = 0; k < 64; k++) {
                    float2 c = cd[k];
                    uint32_t u0 = w0[k], u1 = w1[k];
                    __nv_bfloat162 p0 = *reinterpret_cast<__nv_bfloat162*>(&u0);
                    __nv_bfloat162 p1 = *reinterpret_cast<__nv_bfloat162*>(&u1);
                    a0 += c.x * __bfloat162float(p0.x) + c.y * __bfloat162float(p0.y);
                    a1 += c.x * __bfloat162float(p1.x) + c.y * __bfloat162float(p1.y);
                }
                vbufN[nA] = a0 + b1s[nA];
                vbufN[nB] = a1 + b1s[nB];
            }
        }
        __syncthreads();   // batch boundary: buffers swap
    }
}

// ---------------------------------------------------------------------------
// K2: logit[r] = relu([ui|cand]@mlp1 + b1) @ mlp2 + b2
// ---------------------------------------------------------------------------
#define K2_SMEM (32 * 256 * 4 + 2 * 16 * 256 * 4)   // 65536

__global__ __launch_bounds__(256, 1) void din_mlp_kernel(
    const float* __restrict__ cand,
    const float* __restrict__ w1, const float* __restrict__ b1,
    const float* __restrict__ w2, const float* __restrict__ b2,
    float* __restrict__ out, int nb)
{
    extern __shared__ __align__(16) float s2[];
    float* xs = s2;              // 32 x 256
    float* ws = s2 + 8192;       // 2 x 16 x 256
    const uint32_t wsA = smem_u32(ws);

    const int tid = threadIdx.x, lane = tid & 31, w = tid >> 5;
    const int rb = blockIdx.x * 32;

#pragma unroll
    for (int i = 0; i < 4; i++) {
        int idx = tid + i * 256;
        int r = idx >> 5, c4 = idx & 31;
        ((float4*)xs)[r * 64 + c4]      = ((const float4*)(g_ui + (size_t)(rb + r) * 128))[c4];
        ((float4*)xs)[r * 64 + 32 + c4] = ((const float4*)(cand + (size_t)(rb + r) * 128))[c4];
    }

    auto issue = [&](int kt, int buf) {
        const float4* src = (const float4*)(w1 + (size_t)kt * 4096);
        uint32_t dst = wsA + (uint32_t)buf * 16384u + (uint32_t)tid * 16u;
#pragma unroll
        for (int i = 0; i < 4; i++)
            asm volatile("cp.async.cg.shared.global [%0], [%1], 16;"
                         :: "r"(dst + i * 4096u), "l"(src + tid + i * 256) : "memory");
    };
    issue(0, 0);
    asm volatile("cp.async.commit_group;" ::: "memory");

    float b1l[8], w2l[8];
#pragma unroll
    for (int j = 0; j < 8; j++) {
        b1l[j] = b1[lane * 8 + j];
        w2l[j] = w2[lane * 8 + j];
    }
    float acc[4][8];
#pragma unroll
    for (int i = 0; i < 4; i++)
#pragma unroll
        for (int j = 0; j < 8; j++) acc[i][j] = 0.f;

    for (int kt = 0; kt < 16; kt++) {
        asm volatile("cp.async.wait_group 0;" ::: "memory");
        __syncthreads();
        if (kt < 15) {
            issue(kt + 1, (kt + 1) & 1);
            asm volatile("cp.async.commit_group;" ::: "memory");
        }
        const float* wt = ws + (kt & 1) * 4096;
#pragma unroll
        for (int kk = 0; kk < 16; kk++) {
            int k = kt * 16 + kk;
            float x0 = xs[(4 * w + 0) * 256 + k];
            float x1 = xs[(4 * w + 1) * 256 + k];
            float x2 = xs[(4 * w + 2) * 256 + k];
            float x3 = xs[(4 * w + 3) * 256 + k];
            float4 a4 = *(const float4*)(wt + kk * 256 + lane * 8);
            float4 c4 = *(const float4*)(wt + kk * 256 + lane * 8 + 4);
            float wb[8] = {a4.x, a4.y, a4.z, a4.w, c4.x, c4.y, c4.z, c4.w};
#pragma unroll
            for (int j = 0; j < 8; j++) {
                acc[0][j] += x0 * wb[j];
                acc[1][j] += x1 * wb[j];
                acc[2][j] += x2 * wb[j];
                acc[3][j] += x3 * wb[j];
            }
        }
    }

    float p[4];
#pragma unroll
    for (int i = 0; i < 4; i++) {
        float s = 0.f;
#pragma unroll
        for (int j = 0; j < 8; j++)
            s += fmaxf(acc[i][j] + b1l[j], 0.f) * w2l[j];
        p[i] = s;
    }
#pragma unroll
    for (int o = 16; o; o >>= 1) {
#pragma unroll
        for (int i = 0; i < 4; i++)
            p[i] += __shfl_xor_sync(0xffffffffu, p[i], o);
    }
    if (lane == 0) {
        float bb = b2[0];
#pragma unroll
        for (int i = 0; i < 4; i++)
            out[rb + 4 * w + i] = p[i] + bb;
    }
}

// ---------------------------------------------------------------------------
extern "C" void kernel_launch(void* const* d_in, const int* in_sizes, int n_in,
                              void* d_out, int out_size)
{
    const float* beh  = (const float*)d_in[0];
    const float* cand = (const float*)d_in[1];
    const float* fc1w = (const float*)d_in[2];
    const float* fc1b = (const float*)d_in[3];
    const float* fc2w = (const float*)d_in[4];
    // d_in[5] = fc2_b: softmax shift-invariant, unused.
    const float* m1w  = (const float*)d_in[6];
    const float* m1b  = (const float*)d_in[7];
    const float* m2w  = (const float*)d_in[8];
    const float* m2b  = (const float*)d_in[9];
    float* out = (float*)d_out;

    const int nb = in_sizes[1] / 128;   // 4096

    int sms = 148;
    cudaDeviceGetAttribute(&sms, cudaDevAttrMultiProcessorCount, 0);

    cudaFuncSetAttribute(din_attn_kernel,
                         cudaFuncAttributeMaxDynamicSharedMemorySize, SMEM_REQ);
    cudaFuncSetAttribute(din_mlp_kernel,
                         cudaFuncAttributeMaxDynamicSharedMemorySize, K2_SMEM);

    int grid1 = sms < nb ? sms : nb;
    din_attn_kernel<<<grid1, 256, SMEM_REQ>>>(beh, cand, fc1w, fc1b, fc2w, nb);

    din_mlp_kernel<<<nb / 32, 256, K2_SMEM>>>(cand, m1w, m1b, m2w, m2b, out, nb);
}

// round 8
// speedup vs baseline: 2.5730x; 2.5730x over previous
#include <cuda_runtime.h>
#include <cuda_bf16.h>
#include <cstdint>

// DIN fused kernels for sm_103a — round 8.
// K1 = round-5 structure (all 256 threads in every phase, bf16 mma + ldmatrix)
//      + cp.async single-staging pipeline: batch b+1's X/cand stream in the
//      background while batch b computes. Only the fp32->bf16 convert is serial.
// K2 = round-5 MLP (fp32, cp.async double-buffered w1).

#define S_LEN 200
#define E_DIM 128
#define XSTRB 272        // bf16 X row stride bytes (17 x 16B, odd -> LDSM conflict-free)

// ---- K1 smem byte offsets ----
#define XBF_OFF    0          // 208 x 136 bf16 = 56576 (rows 200-207 zero)
#define STG_OFF    56576      // 200x128 fp32 X staging (102400) + 128 fp32 cand (512)
#define STGC_OFF   158976     // staged cand
#define WC_OFF     159488     // 128 x 132 bf16 W_c^T [n][e] = 33792
#define VBUF_OFF   193280     // float[128]
#define PART_OFF   193792     // float[960]
#define RED_OFF    197632     // float[64]
#define B1_OFF     197888     // float[128]
#define SMEM_REQ   198400

__device__ float g_ui[4096 * 128];   // user_interest

__device__ __forceinline__ uint32_t smem_u32(const void* p) {
    uint32_t a;
    asm("{ .reg .u64 t; cvta.to.shared.u64 t, %1; cvt.u32.u64 %0, t; }"
        : "=r"(a) : "l"(p));
    return a;
}
__device__ __forceinline__ uint32_t packbf(float lo, float hi) {
    uint32_t r;  // first f32 source -> high half
    asm("cvt.rn.bf16x2.f32 %0, %1, %2;" : "=r"(r) : "f"(hi), "f"(lo));
    return r;
}
__device__ __forceinline__ void mma16(float* d, const uint32_t* a, const uint32_t* b) {
    asm volatile(
        "mma.sync.aligned.m16n8k16.row.col.f32.bf16.bf16.f32 "
        "{%0,%1,%2,%3}, {%4,%5,%6,%7}, {%8,%9}, {%0,%1,%2,%3};"
        : "+f"(d[0]), "+f"(d[1]), "+f"(d[2]), "+f"(d[3])
        : "r"(a[0]), "r"(a[1]), "r"(a[2]), "r"(a[3]), "r"(b[0]), "r"(b[1]));
}
__device__ __forceinline__ void ldsm4(uint32_t* r, uint32_t addr) {
    asm volatile("ldmatrix.sync.aligned.m8n8.x4.shared.b16 {%0,%1,%2,%3}, [%4];"
                 : "=r"(r[0]), "=r"(r[1]), "=r"(r[2]), "=r"(r[3]) : "r"(addr));
}

// ---------------------------------------------------------------------------
// K1: persistent fused attention. 256 threads, 8 warps, 1 CTA/SM.
// wc = wid&3 owns h-cols [32wc,32wc+32) (W_b B-frags in 64 regs),
// wrh = wid>>2 owns row half (mt 0..6 / 7..12).
// ---------------------------------------------------------------------------
__global__ __launch_bounds__(256, 1) void din_attn_kernel(
    const float* __restrict__ beh, const float* __restrict__ cand,
    const float* __restrict__ fc1w, const float* __restrict__ fc1b,
    const float* __restrict__ fc2w, int nb)
{
    extern __shared__ __align__(16) char Ab[];
    const uint32_t A = smem_u32(Ab);

    float* stgF  = (float*)(Ab + STG_OFF);
    float* candsS= (float*)(Ab + STGC_OFF);
    float* vbuf  = (float*)(Ab + VBUF_OFF);
    float* part  = (float*)(Ab + PART_OFF);
    float* red   = (float*)(Ab + RED_OFF);
    float* b1s   = (float*)(Ab + B1_OFF);

    const int tid = threadIdx.x, wid = tid >> 5, lane = tid & 31;
    const int g = lane >> 2, t4 = lane & 3;
    const int wc = wid & 3, wrh = wid >> 2;
    const int n0 = wc * 32;
    const int stride = gridDim.x;
    const int b0 = blockIdx.x;
    if (b0 >= nb) return;

    // ================= one-time init =================
    {   // stage W_b fp32 into staging region (coalesced)
        const float4* w4 = (const float4*)fc1w;
        float4* s4 = (float4*)stgF;
#pragma unroll
        for (int i = 0; i < 16; i++) s4[tid + i * 256] = w4[tid + i * 256];
    }
    __syncthreads();
    uint32_t Bf[8][4][2];
#pragma unroll
    for (int kt = 0; kt < 8; kt++)
#pragma unroll
        for (int nt = 0; nt < 4; nt++) {
            int n = n0 + nt * 8 + g;
            int r = kt * 16 + 2 * t4;
            Bf[kt][nt][0] = packbf(stgF[r * 128 + n],       stgF[(r + 1) * 128 + n]);
            Bf[kt][nt][1] = packbf(stgF[(r + 8) * 128 + n], stgF[(r + 9) * 128 + n]);
        }
    float w2v[4][2];
#pragma unroll
    for (int nt = 0; nt < 4; nt++) {
        w2v[nt][0] = fc2w[n0 + nt * 8 + 2 * t4];
        w2v[nt][1] = fc2w[n0 + nt * 8 + 2 * t4 + 1];
    }
    __syncthreads();   // staging consumed

    // W_c -> bf16 [n][e] stride 132; b1; zero phantom X rows
    for (int idx = tid; idx < 128 * 128; idx += 256) {
        int e = idx >> 7, n = idx & 127;
        *(__nv_bfloat16*)(Ab + WC_OFF + (uint32_t)(n * 132 + e) * 2) =
            __float2bfloat16_rn(fc1w[128 * 128 + idx]);
    }
    if (tid < 128) b1s[tid] = fc1b[tid];
    for (int i = tid; i < 1088; i += 256)
        *(uint16_t*)(Ab + XBF_OFF + 200 * XSTRB + i * 2) = 0;

    // cp.async batch b's X (+cand) into staging — fire and forget
    auto issue_load = [&](int b) {
        const float4* src = (const float4*)(beh + (size_t)b * (S_LEN * E_DIM));
        uint32_t dst = A + STG_OFF + (uint32_t)tid * 16u;
#pragma unroll
        for (int it = 0; it < 25; it++)
            asm volatile("cp.async.cg.shared.global [%0], [%1], 16;"
                         :: "r"(dst + it * 4096u), "l"(src + tid + it * 256) : "memory");
        if (tid < 32)
            asm volatile("cp.async.cg.shared.global [%0], [%1], 16;"
                         :: "r"(A + STGC_OFF + (uint32_t)tid * 16u),
                            "l"((const float4*)(cand + (size_t)b * 128) + tid) : "memory");
    };
    issue_load(b0);
    asm volatile("cp.async.commit_group;" ::: "memory");

    const uint32_t lm_base = A + XBF_OFF + (uint32_t)(lane & 15) * XSTRB
                           + ((lane & 16) ? 16u : 0u);
    const int mt_begin = wrh ? 7 : 0;
    const int mt_end   = wrh ? 13 : 7;

    // ================= main loop =================
    for (int b = b0; b < nb; b += stride) {
        asm volatile("cp.async.wait_group 0;" ::: "memory");
        __syncthreads();   // staging ready AND prev batch's XBF readers done

        // ---- convert staging fp32 -> XBF bf16 (swizzled) ----
#pragma unroll
        for (int it = 0; it < 25; it++) {
            int i = tid + it * 256;
            float4 v = ((const float4*)stgF)[i];
            int s = i >> 5, e0 = (i & 31) * 4;
            *(uint2*)(Ab + XBF_OFF + (uint32_t)s * XSTRB + (uint32_t)e0 * 2) =
                make_uint2(packbf(v.x, v.y), packbf(v.z, v.w));
        }
        // stash staged cand into regs before next issue overwrites nothing
        // (cand staging area is only rewritten by next issue_load; gemv reads it
        //  before that point is reached? No — issue happens first. Copy to regs.)
        float2 cd0, cd1;
        {
            int h2 = tid & 1;
            const float2* cd = (const float2*)candsS + h2 * 32;
            cd0 = cd[0];  // dummy init to satisfy compiler; real reads below
            (void)cd0; (void)cd1;
        }
        __syncthreads();   // XBF ready; staging free to refill

        // ---- gemv v = cand@W_c + b1 BEFORE reissuing staging ----
        {
            int n = tid >> 1, h2 = tid & 1;
            const uint32_t* wrow = (const uint32_t*)(Ab + WC_OFF) + n * 66 + h2 * 32;
            const float2* cd = (const float2*)candsS + h2 * 32;
            float a = 0.f;
#pragma unroll 8
            for (int k = 0; k < 32; k++) {
                uint32_t wv = wrow[k];
                __nv_bfloat162 p = *reinterpret_cast<__nv_bfloat162*>(&wv);
                float2 c = cd[k];
                a += c.x * __bfloat162float(p.x) + c.y * __bfloat162float(p.y);
            }
            a += __shfl_xor_sync(0xffffffffu, a, 1);
            if (h2 == 0) vbuf[n] = a + b1s[n];
        }
        __syncthreads();   // vbuf visible; cand staging consumed

        // ---- now refill staging for b+stride (overlaps mma/softmax/ui) ----
        if (b + stride < nb) issue_load(b + stride);
        asm volatile("cp.async.commit_group;" ::: "memory");

        float2 vv[4];
#pragma unroll
        for (int nt = 0; nt < 4; nt++)
            vv[nt] = *(const float2*)(vbuf + n0 + nt * 8 + 2 * t4);

        // ---- mma: h = relu(X@W_b + v); per-row score partials ----
        for (int mt = mt_begin; mt < mt_end; mt++) {
            uint32_t abase = lm_base + (uint32_t)mt * 16u * XSTRB;
            float acc[4][4];
#pragma unroll
            for (int nt = 0; nt < 4; nt++)
#pragma unroll
                for (int j = 0; j < 4; j++) acc[nt][j] = 0.f;
#pragma unroll
            for (int kt = 0; kt < 8; kt++) {
                uint32_t a[4];
                ldsm4(a, abase + (uint32_t)kt * 32u);
                mma16(acc[0], a, Bf[kt][0]);
                mma16(acc[1], a, Bf[kt][1]);
                mma16(acc[2], a, Bf[kt][2]);
                mma16(acc[3], a, Bf[kt][3]);
            }
            float p0 = 0.f, p1 = 0.f;
#pragma unroll
            for (int nt = 0; nt < 4; nt++) {
                p0 += fmaxf(acc[nt][0] + vv[nt].x, 0.f) * w2v[nt][0]
                    + fmaxf(acc[nt][1] + vv[nt].y, 0.f) * w2v[nt][1];
                p1 += fmaxf(acc[nt][2] + vv[nt].x, 0.f) * w2v[nt][0]
                    + fmaxf(acc[nt][3] + vv[nt].y, 0.f) * w2v[nt][1];
            }
            p0 += __shfl_xor_sync(0xffffffffu, p0, 1);
            p0 += __shfl_xor_sync(0xffffffffu, p0, 2);
            p1 += __shfl_xor_sync(0xffffffffu, p1, 1);
            p1 += __shfl_xor_sync(0xffffffffu, p1, 2);
            if (t4 == 0) {
                int r_lo = mt * 16 + g, r_hi = mt * 16 + 8 + g;
                part[wc * 208 + r_lo] = p0;
                if (r_hi < S_LEN) part[wc * 208 + r_hi] = p1;
            }
        }
        __syncthreads();

        // ---- softmax over 200 scores ----
        float sc = -3.4e38f;
        if (tid < S_LEN)
            sc = part[tid] + part[208 + tid] + part[416 + tid] + part[624 + tid];
        float mx = sc;
#pragma unroll
        for (int o = 16; o; o >>= 1) mx = fmaxf(mx, __shfl_xor_sync(0xffffffffu, mx, o));
        if (lane == 0) red[wid] = mx;
        __syncthreads();
        mx = red[0];
#pragma unroll
        for (int w = 1; w < 8; w++) mx = fmaxf(mx, red[w]);
        float ex = (tid < S_LEN) ? __expf(sc - mx) : 0.f;
        float sum = ex;
#pragma unroll
        for (int o = 16; o; o >>= 1) sum += __shfl_xor_sync(0xffffffffu, sum, o);
        if (lane == 0) red[8 + wid] = sum;
        __syncthreads();
        sum = 0.f;
#pragma unroll
        for (int w = 0; w < 8; w++) sum += red[8 + w];
        if (tid < S_LEN) part[tid] = ex / sum;   // attn weights
        __syncthreads();

        // ---- user_interest = attn @ X (bf16) ----
        {
            int e = tid & 127, h = tid >> 7;
            float acc = 0.f;
            int s0 = h * 100;
#pragma unroll 4
            for (int s = s0; s < s0 + 100; s++)
                acc += part[s] * __bfloat162float(
                    *(const __nv_bfloat16*)(Ab + XBF_OFF + (uint32_t)s * XSTRB + (uint32_t)e * 2));
            if (h == 1) part[832 + e] = acc;
            __syncthreads();
            if (h == 0) g_ui[(size_t)b * 128 + e] = acc + part[832 + e];
        }
    }
}

// ---------------------------------------------------------------------------
// K2: logit[r] = relu([ui|cand]@mlp1 + b1) @ mlp2 + b2
// ---------------------------------------------------------------------------
#define K2_SMEM (32 * 256 * 4 + 2 * 16 * 256 * 4)   // 65536

__global__ __launch_bounds__(256, 1) void din_mlp_kernel(
    const float* __restrict__ cand,
    const float* __restrict__ w1, const float* __restrict__ b1,
    const float* __restrict__ w2, const float* __restrict__ b2,
    float* __restrict__ out, int nb)
{
    extern __shared__ __align__(16) float s2[];
    float* xs = s2;              // 32 x 256
    float* ws = s2 + 8192;       // 2 x 16 x 256
    const uint32_t wsA = smem_u32(ws);

    const int tid = threadIdx.x, lane = tid & 31, w = tid >> 5;
    const int rb = blockIdx.x * 32;

#pragma unroll
    for (int i = 0; i < 4; i++) {
        int idx = tid + i * 256;
        int r = idx >> 5, c4 = idx & 31;
        ((float4*)xs)[r * 64 + c4]      = ((const float4*)(g_ui + (size_t)(rb + r) * 128))[c4];
        ((float4*)xs)[r * 64 + 32 + c4] = ((const float4*)(cand + (size_t)(rb + r) * 128))[c4];
    }

    auto issue = [&](int kt, int buf) {
        const float4* src = (const float4*)(w1 + (size_t)kt * 4096);
        uint32_t dst = wsA + (uint32_t)buf * 16384u + (uint32_t)tid * 16u;
#pragma unroll
        for (int i = 0; i < 4; i++)
            asm volatile("cp.async.cg.shared.global [%0], [%1], 16;"
                         :: "r"(dst + i * 4096u), "l"(src + tid + i * 256) : "memory");
    };
    issue(0, 0);
    asm volatile("cp.async.commit_group;" ::: "memory");

    float b1l[8], w2l[8];
#pragma unroll
    for (int j = 0; j < 8; j++) {
        b1l[j] = b1[lane * 8 + j];
        w2l[j] = w2[lane * 8 + j];
    }
    float acc[4][8];
#pragma unroll
    for (int i = 0; i < 4; i++)
#pragma unroll
        for (int j = 0; j < 8; j++) acc[i][j] = 0.f;

    for (int kt = 0; kt < 16; kt++) {
        asm volatile("cp.async.wait_group 0;" ::: "memory");
        __syncthreads();
        if (kt < 15) {
            issue(kt + 1, (kt + 1) & 1);
            asm volatile("cp.async.commit_group;" ::: "memory");
        }
        const float* wt = ws + (kt & 1) * 4096;
#pragma unroll
        for (int kk = 0; kk < 16; kk++) {
            int k = kt * 16 + kk;
            float x0 = xs[(4 * w + 0) * 256 + k];
            float x1 = xs[(4 * w + 1) * 256 + k];
            float x2 = xs[(4 * w + 2) * 256 + k];
            float x3 = xs[(4 * w + 3) * 256 + k];
            float4 a4 = *(const float4*)(wt + kk * 256 + lane * 8);
            float4 c4 = *(const float4*)(wt + kk * 256 + lane * 8 + 4);
            float wb[8] = {a4.x, a4.y, a4.z, a4.w, c4.x, c4.y, c4.z, c4.w};
#pragma unroll
            for (int j = 0; j < 8; j++) {
                acc[0][j] += x0 * wb[j];
                acc[1][j] += x1 * wb[j];
                acc[2][j] += x2 * wb[j];
                acc[3][j] += x3 * wb[j];
            }
        }
    }

    float p[4];
#pragma unroll
    for (int i = 0; i < 4; i++) {
        float s = 0.f;
#pragma unroll
        for (int j = 0; j < 8; j++)
            s += fmaxf(acc[i][j] + b1l[j], 0.f) * w2l[j];
        p[i] = s;
    }
#pragma unroll
    for (int o = 16; o; o >>= 1) {
#pragma unroll
        for (int i = 0; i < 4; i++)
            p[i] += __shfl_xor_sync(0xffffffffu, p[i], o);
    }
    if (lane == 0) {
        float bb = b2[0];
#pragma unroll
        for (int i = 0; i < 4; i++)
            out[rb + 4 * w + i] = p[i] + bb;
    }
}

// ---------------------------------------------------------------------------
extern "C" void kernel_launch(void* const* d_in, const int* in_sizes, int n_in,
                              void* d_out, int out_size)
{
    const float* beh  = (const float*)d_in[0];
    const float* cand = (const float*)d_in[1];
    const float* fc1w = (const float*)d_in[2];
    const float* fc1b = (const float*)d_in[3];
    const float* fc2w = (const float*)d_in[4];
    // d_in[5] = fc2_b: softmax shift-invariant, unused.
    const float* m1w  = (const float*)d_in[6];
    const float* m1b  = (const float*)d_in[7];
    const float* m2w  = (const float*)d_in[8];
    const float* m2b  = (const float*)d_in[9];
    float* out = (float*)d_out;

    const int nb = in_sizes[1] / 128;   // 4096

    int sms = 148;
    cudaDeviceGetAttribute(&sms, cudaDevAttrMultiProcessorCount, 0);

    cudaFuncSetAttribute(din_attn_kernel,
                         cudaFuncAttributeMaxDynamicSharedMemorySize, SMEM_REQ);
    cudaFuncSetAttribute(din_mlp_kernel,
                         cudaFuncAttributeMaxDynamicSharedMemorySize, K2_SMEM);

    int grid1 = sms < nb ? sms : nb;
    din_attn_kernel<<<grid1, 256, SMEM_REQ>>>(beh, cand, fc1w, fc1b, fc2w, nb);

    din_mlp_kernel<<<nb / 32, 256, K2_SMEM>>>(cand, m1w, m1b, m2w, m2b, out, nb);
}

// round 11
// speedup vs baseline: 2.7181x; 1.0564x over previous
#include <cuda_runtime.h>
#include <cuda_bf16.h>
#include <cstdint>

// DIN fused kernels for sm_103a — round 10.
// K1: round-9 attention (col-groups=2, wide ui) — halved smem-crossbar traffic.
// K2: round-8 fp32 MLP (known-good precision; bf16 MLP failed rel_err).

#define S_LEN 200
#define E_DIM 128
#define XSTRB 272        // bf16 X row stride bytes (17 x 16B, odd -> LDSM conflict-free)

// ---- K1 smem byte offsets ----
#define XBF_OFF    0          // 208 x 136 bf16 = 56576 (rows 200-207 zero)
#define STG_OFF    56576      // 200x128 fp32 X staging = 102400
#define STGC_OFF   158976     // staged cand, 512
#define WC_OFF     159488     // 128 x 132 bf16 W_c^T [n][e] = 33792
#define VBUF_OFF   193280     // float[128] v = cand@W_c + b1
#define PART_OFF   193792     // float[416] score partials / attn(200)
#define PART2_OFF  195456     // float[1024] ui partials [8][128]
#define RED_OFF    199552     // float[64]
#define B1_OFF     199808     // float[128]
#define W2S_OFF    200320     // float[128]
#define SMEM_REQ   200832

__device__ float g_ui[4096 * 128];   // user_interest

__device__ __forceinline__ uint32_t smem_u32(const void* p) {
    uint32_t a;
    asm("{ .reg .u64 t; cvta.to.shared.u64 t, %1; cvt.u32.u64 %0, t; }"
        : "=r"(a) : "l"(p));
    return a;
}
__device__ __forceinline__ uint32_t packbf(float lo, float hi) {
    uint32_t r;  // first f32 source -> high half
    asm("cvt.rn.bf16x2.f32 %0, %1, %2;" : "=r"(r) : "f"(hi), "f"(lo));
    return r;
}
__device__ __forceinline__ float2 bf2f(uint32_t u) {
    __nv_bfloat162 p = *reinterpret_cast<__nv_bfloat162*>(&u);
    return make_float2(__bfloat162float(p.x), __bfloat162float(p.y));
}
__device__ __forceinline__ void mma16(float* d, const uint32_t* a, const uint32_t* b) {
    asm volatile(
        "mma.sync.aligned.m16n8k16.row.col.f32.bf16.bf16.f32 "
        "{%0,%1,%2,%3}, {%4,%5,%6,%7}, {%8,%9}, {%0,%1,%2,%3};"
        : "+f"(d[0]), "+f"(d[1]), "+f"(d[2]), "+f"(d[3])
        : "r"(a[0]), "r"(a[1]), "r"(a[2]), "r"(a[3]), "r"(b[0]), "r"(b[1]));
}
__device__ __forceinline__ void ldsm4(uint32_t* r, uint32_t addr) {
    asm volatile("ldmatrix.sync.aligned.m8n8.x4.shared.b16 {%0,%1,%2,%3}, [%4];"
                 : "=r"(r[0]), "=r"(r[1]), "=r"(r[2]), "=r"(r[3]) : "r"(addr));
}

// ---------------------------------------------------------------------------
// K1: 256 threads, 8 warps, 1 CTA/SM.
// wc = wid&1 owns h-cols [64wc, 64wc+64) (Bf = 128 regs),
// rg = wid>>1 owns mt range {0-3, 4-6, 7-9, 10-12}.
// ---------------------------------------------------------------------------
__global__ __launch_bounds__(256, 1) void din_attn_kernel(
    const float* __restrict__ beh, const float* __restrict__ cand,
    const float* __restrict__ fc1w, const float* __restrict__ fc1b,
    const float* __restrict__ fc2w, int nb)
{
    extern __shared__ __align__(16) char Ab[];
    const uint32_t A = smem_u32(Ab);

    float* stgF  = (float*)(Ab + STG_OFF);
    float* candsS= (float*)(Ab + STGC_OFF);
    float* vbuf  = (float*)(Ab + VBUF_OFF);
    float* part  = (float*)(Ab + PART_OFF);
    float* part2 = (float*)(Ab + PART2_OFF);
    float* red   = (float*)(Ab + RED_OFF);
    float* b1s   = (float*)(Ab + B1_OFF);
    float* w2s   = (float*)(Ab + W2S_OFF);

    const int tid = threadIdx.x, wid = tid >> 5, lane = tid & 31;
    const int g = lane >> 2, t4 = lane & 3;
    const int wc = wid & 1, rg = wid >> 1;
    const int n0 = wc * 64;
    const int stride = gridDim.x;
    const int b0 = blockIdx.x;
    if (b0 >= nb) return;

    static const int mtb[5] = {0, 4, 7, 10, 13};
    const int mt_begin = mtb[rg], mt_end = mtb[rg + 1];

    // ================= one-time init =================
    {   // stage W_b fp32 into staging region
        const float4* w4 = (const float4*)fc1w;
        float4* s4 = (float4*)stgF;
#pragma unroll
        for (int i = 0; i < 16; i++) s4[tid + i * 256] = w4[tid + i * 256];
    }
    __syncthreads();
    uint32_t Bf[8][8][2];
#pragma unroll
    for (int kt = 0; kt < 8; kt++)
#pragma unroll
        for (int nt = 0; nt < 8; nt++) {
            int n = n0 + nt * 8 + g;
            int r = kt * 16 + 2 * t4;
            Bf[kt][nt][0] = packbf(stgF[r * 128 + n],       stgF[(r + 1) * 128 + n]);
            Bf[kt][nt][1] = packbf(stgF[(r + 8) * 128 + n], stgF[(r + 9) * 128 + n]);
        }
    __syncthreads();   // staging consumed

    for (int idx = tid; idx < 128 * 128; idx += 256) {
        int e = idx >> 7, n = idx & 127;
        *(__nv_bfloat16*)(Ab + WC_OFF + (uint32_t)(n * 132 + e) * 2) =
            __float2bfloat16_rn(fc1w[128 * 128 + idx]);
    }
    if (tid < 128) { b1s[tid] = fc1b[tid]; w2s[tid] = fc2w[tid]; }
    for (int i = tid; i < 1088; i += 256)
        *(uint16_t*)(Ab + XBF_OFF + 200 * XSTRB + i * 2) = 0;

    auto issue_load = [&](int b) {
        const float4* src = (const float4*)(beh + (size_t)b * (S_LEN * E_DIM));
        uint32_t dst = A + STG_OFF + (uint32_t)tid * 16u;
#pragma unroll
        for (int it = 0; it < 25; it++)
            asm volatile("cp.async.cg.shared.global [%0], [%1], 16;"
                         :: "r"(dst + it * 4096u), "l"(src + tid + it * 256) : "memory");
        if (tid < 32)
            asm volatile("cp.async.cg.shared.global [%0], [%1], 16;"
                         :: "r"(A + STGC_OFF + (uint32_t)tid * 16u),
                            "l"((const float4*)(cand + (size_t)b * 128) + tid) : "memory");
    };
    issue_load(b0);
    asm volatile("cp.async.commit_group;" ::: "memory");

    const uint32_t lm_base = A + XBF_OFF + (uint32_t)(lane & 15) * XSTRB
                           + ((lane & 16) ? 16u : 0u);

    // ================= main loop =================
    for (int b = b0; b < nb; b += stride) {
        asm volatile("cp.async.wait_group 0;" ::: "memory");
        __syncthreads();   // staging ready AND prev batch's readers done

        // ---- convert staging fp32 -> XBF bf16 (swizzled) ----
#pragma unroll
        for (int it = 0; it < 25; it++) {
            int i = tid + it * 256;
            float4 v = ((const float4*)stgF)[i];
            int s = i >> 5, e0 = (i & 31) * 4;
            *(uint2*)(Ab + XBF_OFF + (uint32_t)s * XSTRB + (uint32_t)e0 * 2) =
                make_uint2(packbf(v.x, v.y), packbf(v.z, v.w));
        }
        __syncthreads();   // XBF ready

        // ---- gemv v = cand@W_c + b1 (reads staged cand) ----
        {
            int n = tid >> 1, h2 = tid & 1;
            const uint32_t* wrow = (const uint32_t*)(Ab + WC_OFF) + n * 66 + h2 * 32;
            const float2* cd = (const float2*)candsS + h2 * 32;
            float a = 0.f;
#pragma unroll 8
            for (int k = 0; k < 32; k++) {
                float2 p = bf2f(wrow[k]);
                float2 c = cd[k];
                a += c.x * p.x + c.y * p.y;
            }
            a += __shfl_xor_sync(0xffffffffu, a, 1);
            if (h2 == 0) vbuf[n] = a + b1s[n];
        }
        __syncthreads();   // vbuf visible; staging free

        if (b + stride < nb) issue_load(b + stride);
        asm volatile("cp.async.commit_group;" ::: "memory");

        // ---- mma: h = relu(X@W_b + v); per-row score partials ----
        for (int mt = mt_begin; mt < mt_end; mt++) {
            uint32_t abase = lm_base + (uint32_t)mt * 16u * XSTRB;
            float acc[8][4];
#pragma unroll
            for (int nt = 0; nt < 8; nt++)
#pragma unroll
                for (int j = 0; j < 4; j++) acc[nt][j] = 0.f;
#pragma unroll
            for (int kt = 0; kt < 8; kt++) {
                uint32_t a[4];
                ldsm4(a, abase + (uint32_t)kt * 32u);
#pragma unroll
                for (int nt = 0; nt < 8; nt++)
                    mma16(acc[nt], a, Bf[kt][nt]);
            }
            float p0 = 0.f, p1 = 0.f;
#pragma unroll
            for (int nt = 0; nt < 8; nt++) {
                int c = n0 + nt * 8 + 2 * t4;
                float2 vv = *(const float2*)(vbuf + c);
                float2 ww = *(const float2*)(w2s + c);
                p0 += fmaxf(acc[nt][0] + vv.x, 0.f) * ww.x
                    + fmaxf(acc[nt][1] + vv.y, 0.f) * ww.y;
                p1 += fmaxf(acc[nt][2] + vv.x, 0.f) * ww.x
                    + fmaxf(acc[nt][3] + vv.y, 0.f) * ww.y;
            }
            p0 += __shfl_xor_sync(0xffffffffu, p0, 1);
            p0 += __shfl_xor_sync(0xffffffffu, p0, 2);
            p1 += __shfl_xor_sync(0xffffffffu, p1, 1);
            p1 += __shfl_xor_sync(0xffffffffu, p1, 2);
            if (t4 == 0) {
                int r_lo = mt * 16 + g, r_hi = mt * 16 + 8 + g;
                part[wc * 208 + r_lo] = p0;
                if (r_hi < S_LEN) part[wc * 208 + r_hi] = p1;
            }
        }
        __syncthreads();

        // ---- softmax over 200 scores ----
        float sc = -3.4e38f;
        if (tid < S_LEN) sc = part[tid] + part[208 + tid];
        float mx = sc;
#pragma unroll
        for (int o = 16; o; o >>= 1) mx = fmaxf(mx, __shfl_xor_sync(0xffffffffu, mx, o));
        if (lane == 0) red[wid] = mx;
        __syncthreads();
        mx = red[0];
#pragma unroll
        for (int w = 1; w < 8; w++) mx = fmaxf(mx, red[w]);
        float ex = (tid < S_LEN) ? __expf(sc - mx) : 0.f;
        float sum = ex;
#pragma unroll
        for (int o = 16; o; o >>= 1) sum += __shfl_xor_sync(0xffffffffu, sum, o);
        if (lane == 0) red[8 + wid] = sum;
        __syncthreads();
        sum = 0.f;
#pragma unroll
        for (int w = 0; w < 8; w++) sum += red[8 + w];
        if (tid < S_LEN) part[tid] = ex / sum;   // attn weights
        __syncthreads();

        // ---- user_interest = attn @ X : wide loads + 8-group partials ----
        {
            int e4 = (tid & 31) * 4;           // 4 e-values per thread
            int h = tid >> 5;                  // 8 row groups of 25
            float a0 = 0.f, a1 = 0.f, a2 = 0.f, a3 = 0.f;
            int s0 = h * 25;
#pragma unroll 5
            for (int s = s0; s < s0 + 25; s++) {
                float w = part[s];
                uint2 xv = *(const uint2*)(Ab + XBF_OFF + (uint32_t)s * XSTRB + (uint32_t)e4 * 2);
                float2 lo = bf2f(xv.x), hi = bf2f(xv.y);
                a0 += w * lo.x; a1 += w * lo.y;
                a2 += w * hi.x; a3 += w * hi.y;
            }
            *(float4*)(part2 + h * 128 + e4) = make_float4(a0, a1, a2, a3);
            __syncthreads();
            if (tid < 128) {
                float s = 0.f;
#pragma unroll
                for (int hh = 0; hh < 8; hh++) s += part2[hh * 128 + tid];
                g_ui[(size_t)b * 128 + tid] = s;
            }
        }
    }
}

// ---------------------------------------------------------------------------
// K2: logit[r] = relu([ui|cand]@mlp1 + b1) @ mlp2 + b2   (fp32, round-8)
// ---------------------------------------------------------------------------
#define K2_SMEM (32 * 256 * 4 + 2 * 16 * 256 * 4)   // 65536

__global__ __launch_bounds__(256, 1) void din_mlp_kernel(
    const float* __restrict__ cand,
    const float* __restrict__ w1, const float* __restrict__ b1,
    const float* __restrict__ w2, const float* __restrict__ b2,
    float* __restrict__ out, int nb)
{
    extern __shared__ __align__(16) float s2[];
    float* xs = s2;              // 32 x 256
    float* ws = s2 + 8192;       // 2 x 16 x 256
    const uint32_t wsA = smem_u32(ws);

    const int tid = threadIdx.x, lane = tid & 31, w = tid >> 5;
    const int rb = blockIdx.x * 32;

#pragma unroll
    for (int i = 0; i < 4; i++) {
        int idx = tid + i * 256;
        int r = idx >> 5, c4 = idx & 31;
        ((float4*)xs)[r * 64 + c4]      = ((const float4*)(g_ui + (size_t)(rb + r) * 128))[c4];
        ((float4*)xs)[r * 64 + 32 + c4] = ((const float4*)(cand + (size_t)(rb + r) * 128))[c4];
    }

    auto issue = [&](int kt, int buf) {
        const float4* src = (const float4*)(w1 + (size_t)kt * 4096);
        uint32_t dst = wsA + (uint32_t)buf * 16384u + (uint32_t)tid * 16u;
#pragma unroll
        for (int i = 0; i < 4; i++)
            asm volatile("cp.async.cg.shared.global [%0], [%1], 16;"
                         :: "r"(dst + i * 4096u), "l"(src + tid + i * 256) : "memory");
    };
    issue(0, 0);
    asm volatile("cp.async.commit_group;" ::: "memory");

    float b1l[8], w2l[8];
#pragma unroll
    for (int j = 0; j < 8; j++) {
        b1l[j] = b1[lane * 8 + j];
        w2l[j] = w2[lane * 8 + j];
    }
    float acc[4][8];
#pragma unroll
    for (int i = 0; i < 4; i++)
#pragma unroll
        for (int j = 0; j < 8; j++) acc[i][j] = 0.f;

    for (int kt = 0; kt < 16; kt++) {
        asm volatile("cp.async.wait_group 0;" ::: "memory");
        __syncthreads();
        if (kt < 15) {
            issue(kt + 1, (kt + 1) & 1);
            asm volatile("cp.async.commit_group;" ::: "memory");
        }
        const float* wt = ws + (kt & 1) * 4096;
#pragma unroll
        for (int kk = 0; kk < 16; kk++) {
            int k = kt * 16 + kk;
            float x0 = xs[(4 * w + 0) * 256 + k];
            float x1 = xs[(4 * w + 1) * 256 + k];
            float x2 = xs[(4 * w + 2) * 256 + k];
            float x3 = xs[(4 * w + 3) * 256 + k];
            float4 a4 = *(const float4*)(wt + kk * 256 + lane * 8);
            float4 c4 = *(const float4*)(wt + kk * 256 + lane * 8 + 4);
            float wb[8] = {a4.x, a4.y, a4.z, a4.w, c4.x, c4.y, c4.z, c4.w};
#pragma unroll
            for (int j = 0; j < 8; j++) {
                acc[0][j] += x0 * wb[j];
                acc[1][j] += x1 * wb[j];
                acc[2][j] += x2 * wb[j];
                acc[3][j] += x3 * wb[j];
            }
        }
    }

    float p[4];
#pragma unroll
    for (int i = 0; i < 4; i++) {
        float s = 0.f;
#pragma unroll
        for (int j = 0; j < 8; j++)
            s += fmaxf(acc[i][j] + b1l[j], 0.f) * w2l[j];
        p[i] = s;
    }
#pragma unroll
    for (int o = 16; o; o >>= 1) {
#pragma unroll
        for (int i = 0; i < 4; i++)
            p[i] += __shfl_xor_sync(0xffffffffu, p[i], o);
    }
    if (lane == 0) {
        float bb = b2[0];
#pragma unroll
        for (int i = 0; i < 4; i++)
            out[rb + 4 * w + i] = p[i] + bb;
    }
}

// ---------------------------------------------------------------------------
extern "C" void kernel_launch(void* const* d_in, const int* in_sizes, int n_in,
                              void* d_out, int out_size)
{
    const float* beh  = (const float*)d_in[0];
    const float* cand = (const float*)d_in[1];
    const float* fc1w = (const float*)d_in[2];
    const float* fc1b = (const float*)d_in[3];
    const float* fc2w = (const float*)d_in[4];
    // d_in[5] = fc2_b: softmax shift-invariant, unused.
    const float* m1w  = (const float*)d_in[6];
    const float* m1b  = (const float*)d_in[7];
    const float* m2w  = (const float*)d_in[8];
    const float* m2b  = (const float*)d_in[9];
    float* out = (float*)d_out;

    const int nb = in_sizes[1] / 128;   // 4096

    int sms = 148;
    cudaDeviceGetAttribute(&sms, cudaDevAttrMultiProcessorCount, 0);

    cudaFuncSetAttribute(din_attn_kernel,
                         cudaFuncAttributeMaxDynamicSharedMemorySize, SMEM_REQ);
    cudaFuncSetAttribute(din_mlp_kernel,
                         cudaFuncAttributeMaxDynamicSharedMemorySize, K2_SMEM);

    int grid1 = sms < nb ? sms : nb;
    din_attn_kernel<<<grid1, 256, SMEM_REQ>>>(beh, cand, fc1w, fc1b, fc2w, nb);

    din_mlp_kernel<<<nb / 32, 256, K2_SMEM>>>(cand, m1w, m1b, m2w, m2b, out, nb);
}